// round 13
// baseline (speedup 1.0000x reference)
#include <cuda_runtime.h>
#include <math.h>

#define D_MODEL 1024
#define N_EXP   32
#define D_LOW   64
#define N_TOK   1024
#define N_PAIR  (N_TOK * 2)
#define OUT_ELEMS (N_TOK * D_MODEL)
#define KSPLIT  4                    // k3 k-split (each block: 8 sub-chunks of 32)
#define LSPLIT  8                    // k2a logit k-split
#define PS      (N_PAIR * D_LOW)     // 131072 partials per k-slice

// ---------------- scratch ------------------------------------------------------
__device__ float g_wr[N_EXP * D_MODEL];
__device__ int   g_cnt[N_EXP];
__device__ float g_sumprob[N_EXP];
__device__ int   g_btok[N_EXP * N_TOK];
__device__ float g_bwgt[N_EXP * N_TOK];
__device__ int   g_pslot[N_TOK * 2];
__device__ float g_lgp[LSPLIT * N_TOK * N_EXP];  // k-split logit partials
__device__ float g_actp[KSPLIT * PS];            // k-split down partials (2MB)
__device__ float g_acts[PS];                     // gelu(feats), pair-compact
__device__ float g_y[N_PAIR * D_MODEL];          // weighted per-pair up output

// ---------------- helpers ------------------------------------------------------
typedef unsigned long long ull;
#define FFMA2(acc, a, b) asm("fma.rn.f32x2 %0, %1, %2, %0;" : "+l"(acc) : "l"(a), "l"(b))

__device__ __forceinline__ void cp16(float* dst_smem, const float4* src) {
    unsigned d = (unsigned)__cvta_generic_to_shared(dst_smem);
    asm volatile("cp.async.cg.shared.global [%0], [%1], 16;" :: "r"(d), "l"(src));
}
#define CP_COMMIT() asm volatile("cp.async.commit_group;")
#define CP_WAIT0()  asm volatile("cp.async.wait_group 0;")
#define CP_WAIT1()  asm volatile("cp.async.wait_group 1;")

__device__ __forceinline__ float hsum2(ull v) {
    return __uint_as_float((unsigned)v) + __uint_as_float((unsigned)(v >> 32));
}
__device__ __forceinline__ float dot4(float4 a, float4 b) {
    return a.x * b.x + a.y * b.y + a.z * b.z + a.w * b.w;
}
__device__ __forceinline__ float gelu_exact(float v) {
    return 0.5f * v * (1.0f + erff(v * 0.70710678118654752440f));
}
// exclusive prefix of g_cnt at expert e (all 32 lanes participate)
__device__ __forceinline__ int expert_off(int lane, int e) {
    int cc = g_cnt[lane];
    int sc = cc;
#pragma unroll
    for (int o = 1; o < 32; o <<= 1) {
        int v = __shfl_up_sync(0xffffffffu, sc, o);
        if (lane >= o) sc += v;
    }
    return __shfl_sync(0xffffffffu, sc - cc, e);
}

// ---------------- K1: fold router_w into w_down -> g_wr; zero accumulators ----
__global__ void k1_fold(const float* __restrict__ w_down,
                        const float* __restrict__ router_w) {
    __shared__ float rs[D_LOW];
    int tid = threadIdx.x;
    if (blockIdx.x == 0 && tid < N_EXP) { g_cnt[tid] = 0; g_sumprob[tid] = 0.f; }
    if (tid < D_LOW) rs[tid] = router_w[tid];
    __syncthreads();
    int idx = blockIdx.x * 256 + tid;
    int e = idx >> 10;
    int d = idx & (D_MODEL - 1);
    const float* wb = w_down + (e << 6) * D_MODEL + d;
    float acc = 0.f;
#pragma unroll 8
    for (int l = 0; l < D_LOW; l++)
        acc = fmaf(wb[l * D_MODEL], rs[l], acc);
    g_wr[idx] = acc;
}

// ---------------- K2a: logits GEMM, k-split by 8 -------------------------------
__global__ __launch_bounds__(256) void k2a_logits(const float* __restrict__ x) {
    __shared__ float4 xs4[32 * 33];
    __shared__ float4 wr4[32 * 33];
    const int tid = threadIdx.x;
    const int tt = blockIdx.x, kc = blockIdx.y;
    const int t = tid & 31, eg = tid >> 5;
    const float4* x4 = (const float4*)x;
    const float4* w4 = (const float4*)g_wr;

    const int k0q = kc * 32;
#pragma unroll
    for (int i = 0; i < 4; i++) {
        int j = tid + i * 256;
        int r = j >> 5, c = j & 31;
        xs4[r * 33 + c] = x4[(tt * 32 + r) * (D_MODEL / 4) + k0q + c];
        wr4[r * 33 + c] = w4[r * (D_MODEL / 4) + k0q + c];
    }
    __syncthreads();
    float acc0 = 0.f, acc1 = 0.f, acc2 = 0.f, acc3 = 0.f;
#pragma unroll 8
    for (int k4 = 0; k4 < 32; k4++) {
        float4 xv = xs4[t * 33 + k4];
        acc0 += dot4(xv, wr4[(eg * 4 + 0) * 33 + k4]);
        acc1 += dot4(xv, wr4[(eg * 4 + 1) * 33 + k4]);
        acc2 += dot4(xv, wr4[(eg * 4 + 2) * 33 + k4]);
        acc3 += dot4(xv, wr4[(eg * 4 + 3) * 33 + k4]);
    }
    const int n = tt * 32 + t;
    ((float4*)g_lgp)[kc * (N_TOK * N_EXP / 4) + n * 8 + eg] =
        make_float4(acc0, acc1, acc2, acc3);
}

// ---------------- K2c: reduce partials + softmax + top-2 + bucketize ----------
__global__ void k2c_route() {
    const int tid = threadIdx.x;
    const int lane = tid & 31, warp = tid >> 5;
    const int n = blockIdx.x * 8 + warp;

    float v = 0.f;
#pragma unroll
    for (int p = 0; p < LSPLIT; p++)
        v += g_lgp[p * (N_TOK * N_EXP) + n * N_EXP + lane];

    float m = v;
#pragma unroll
    for (int o = 16; o; o >>= 1) m = fmaxf(m, __shfl_xor_sync(0xffffffffu, m, o));
    float ex = expf(v - m);
    float s = ex;
#pragma unroll
    for (int o = 16; o; o >>= 1) s += __shfl_xor_sync(0xffffffffu, s, o);
    float prob = ex / s;
    atomicAdd(&g_sumprob[lane], prob);

    float bv = v; int bi = lane;
#pragma unroll
    for (int o = 16; o; o >>= 1) {
        float ov = __shfl_xor_sync(0xffffffffu, bv, o);
        int   oi = __shfl_xor_sync(0xffffffffu, bi, o);
        if (ov > bv || (ov == bv && oi < bi)) { bv = ov; bi = oi; }
    }
    int i0 = bi;
    float v2 = (lane == i0) ? -INFINITY : v;
    float bv2 = v2; int bi2 = lane;
#pragma unroll
    for (int o = 16; o; o >>= 1) {
        float ov = __shfl_xor_sync(0xffffffffu, bv2, o);
        int   oi = __shfl_xor_sync(0xffffffffu, bi2, o);
        if (ov > bv2 || (ov == bv2 && oi < bi2)) { bv2 = ov; bi2 = oi; }
    }
    int i1 = bi2;
    float p0 = __shfl_sync(0xffffffffu, prob, i0);
    float p1 = __shfl_sync(0xffffffffu, prob, i1);
    if (lane == 0) {
        float inv = 1.f / (p0 + p1);
        int s0 = atomicAdd(&g_cnt[i0], 1);
        g_btok[i0 * N_TOK + s0] = n;
        g_bwgt[i0 * N_TOK + s0] = p0 * inv;
        g_pslot[n * 2 + 0] = i0 * N_TOK + s0;
        int s1 = atomicAdd(&g_cnt[i1], 1);
        g_btok[i1 * N_TOK + s1] = n;
        g_bwgt[i1 * N_TOK + s1] = p1 * inv;
        g_pslot[n * 2 + 1] = i1 * N_TOK + s1;
    }
}

// ---------------- K3: down-proj, cp.async double-buffered 8-sub-chunk pipeline -
// grid (4 k-chunks, 32 experts, 2 token-tiles), 256 threads.
// Block: 64 tok x 64 l x 256 k (8 sub-chunks of 32 k, register-accumulated).
// smem: 2*(64*36 + 64*36)*4 = 36 KB  (under the 48 KB static limit)
__global__ __launch_bounds__(256, 3)
void k3_down(const float* __restrict__ x, const float* __restrict__ w_down) {
    __shared__ __align__(16) float ws[2][D_LOW * 36];   // [64 l][32 k + pad]
    __shared__ __align__(16) float xs[2][64 * 36];      // [64 tok][32 k + pad]

    const int e = blockIdx.y;
    const int kc = blockIdx.x;             // 0..3 -> k range [kc*256, +256)
    const int cnt = g_cnt[e];
    const int tile0 = blockIdx.z * 64;
    if (tile0 >= cnt) return;
    const int tid = threadIdx.x;
    const int off = expert_off(tid & 31, e);

    const float4* wd4 = (const float4*)w_down;
    const float4* x4g = (const float4*)x;

    const int nT = (cnt - tile0 + 127) / 128;
    const int nIter = nT * 8;

    // fill sub-chunk (t0, sc) into buffer b; sub-chunk = 32 k = 8 f4
    auto fill = [&](int b, int t0, int sc) {
        const int kq = kc * 64 + sc * 8;               // f4 offset in k
#pragma unroll
        for (int i = 0; i < 2; i++) {                  // ws: 512 f4
            int j = tid + i * 256;
            int l = j >> 3, cq = j & 7;
            cp16(&ws[b][l * 36 + cq * 4],
                 wd4 + (e * D_LOW + l) * (D_MODEL / 4) + kq + cq);
        }
#pragma unroll
        for (int i = 0; i < 2; i++) {                  // xs: 512 f4
            int j = tid + i * 256;
            int r = j >> 3, cq = j & 7;
            int idx = t0 + r; if (idx >= cnt) idx = cnt - 1;
            int tok = g_btok[e * N_TOK + idx];
            cp16(&xs[b][r * 36 + cq * 4],
                 x4g + tok * (D_MODEL / 4) + kq + cq);
        }
    };

    fill(0, tile0, 0);
    CP_COMMIT();

    const int tq = tid & 15;
    const int lq = tid >> 4;
    ull acc[4][4];
#pragma unroll
    for (int j = 0; j < 4; j++)
#pragma unroll
        for (int i = 0; i < 4; i++) acc[j][i] = 0ull;

    for (int it = 0; it < nIter; it++) {
        const int buf = it & 1;
        const bool more = (it + 1 < nIter);
        if (more) {
            int itn = it + 1;
            fill(itn & 1, tile0 + (itn >> 3) * 128, itn & 7);
            CP_COMMIT();
            CP_WAIT1();
        } else {
            CP_WAIT0();
        }
        __syncthreads();

#pragma unroll
        for (int k4i = 0; k4i < 8; k4i++) {
            ulonglong2 xv[4], wv[4];
#pragma unroll
            for (int j = 0; j < 4; j++)
                xv[j] = *(const ulonglong2*)(&xs[buf][(tq + 16 * j) * 36 + k4i * 4]);
#pragma unroll
            for (int i = 0; i < 4; i++)
                wv[i] = *(const ulonglong2*)(&ws[buf][(lq * 4 + i) * 36 + k4i * 4]);
#pragma unroll
            for (int j = 0; j < 4; j++)
#pragma unroll
                for (int i = 0; i < 4; i++) {
                    FFMA2(acc[j][i], xv[j].x, wv[i].x);
                    FFMA2(acc[j][i], xv[j].y, wv[i].y);
                }
        }

        if ((it & 7) == 7) {                           // last sub-chunk of tile
            const int t0 = tile0 + (it >> 3) * 128;
            float4* ap4 = (float4*)g_actp;
#pragma unroll
            for (int j = 0; j < 4; j++) {
                int s = t0 + tq + 16 * j;
                if (s < cnt) {
                    float4 v = make_float4(hsum2(acc[j][0]), hsum2(acc[j][1]),
                                           hsum2(acc[j][2]), hsum2(acc[j][3]));
                    ap4[(kc * N_PAIR + off + s) * (D_LOW / 4) + lq] = v;
                }
#pragma unroll
                for (int i = 0; i < 4; i++) acc[j][i] = 0ull;
            }
        }
        __syncthreads();
    }
}

// ---------------- K3g: sum 4 k-slices + GELU (+ aux loss in block 0) ----------
__global__ void k3g_gelu(float* out, int write_aux) {
    int tid = threadIdx.x;
    if (blockIdx.x == 0 && tid < 32 && write_aux) {
        float v = g_sumprob[tid] * (float)g_cnt[tid];
#pragma unroll
        for (int o = 16; o; o >>= 1) v += __shfl_xor_sync(0xffffffffu, v, o);
        if (tid == 0)
            out[OUT_ELEMS] = (float)N_EXP * v / ((float)N_TOK * (float)N_TOK);
    }
    int i = blockIdx.x * 256 + tid;               // 128*256 = PS/4
    const float4* ap4 = (const float4*)g_actp;
    float4 s = ap4[i];
#pragma unroll
    for (int k = 1; k < KSPLIT; k++) {
        float4 v = ap4[k * (PS / 4) + i];
        s.x += v.x; s.y += v.y; s.z += v.z; s.w += v.w;
    }
    ((float4*)g_acts)[i] = make_float4(gelu_exact(s.x), gelu_exact(s.y),
                                       gelu_exact(s.z), gelu_exact(s.w));
}

// ---------------- K4: up-proj, 4 d-sub-chunks, reg-double-buffered weights -----
// grid (4 d-groups, 32 experts, 2 token-tiles), 256 threads.
// Block: 64 tok x 256 d (4 sub-chunks of 64 d) x 64 l.  smem 34 KB.
__global__ __launch_bounds__(256, 3)
void k4_up(const float* __restrict__ w_up) {
    __shared__ __align__(16) float wu_s[64 * 68];   // [64 d][64 l + pad] transposed
    __shared__ __align__(16) float as_s[64 * 68];   // [64 tok][64 l + pad]

    const int e = blockIdx.y;
    const int dg = blockIdx.x;             // 0..3 -> d range [dg*256, +256)
    const int cnt = g_cnt[e];
    const int tile0 = blockIdx.z * 64;
    if (tile0 >= cnt) return;
    const int tid = threadIdx.x;
    const int off = expert_off(tid & 31, e);

    const float4* a4g = (const float4*)g_acts;
    float4* y4 = (float4*)g_y;
    const int r0 = tid >> 4, cq0 = tid & 15;
    const int dloc = tid & 63, lg = tid >> 6;   // wu fill coords (4 rows per thread)
    const int tq = tid & 15;
    const int dq = tid >> 4;

    // weight sub-chunk fetch into regs: w_up[e][lg*4 + 0..3][dg*256 + dc*64 + dloc]
    auto wfetch = [&](int dc, float4* wr) {
#pragma unroll
        for (int i = 0; i < 4; i++) {
            const float* base = w_up + (e * D_LOW + (lg + 4 * i) * 4) * D_MODEL
                              + dg * 256 + dc * 64 + dloc;
            wr[i] = make_float4(base[0], base[D_MODEL],
                                base[2 * D_MODEL], base[3 * D_MODEL]);
        }
    };

    for (int t0 = tile0; t0 < cnt; t0 += 128) {
        // async fill of acts tile
#pragma unroll
        for (int jj = 0; jj < 4; jj++) {
            int r = r0 + 16 * jj;
            int idx = t0 + r; if (idx >= cnt) idx = cnt - 1;
            cp16(&as_s[r * 68 + cq0 * 4], a4g + (off + idx) * (D_LOW / 4) + cq0);
        }
        CP_COMMIT();

        float4 wr[4];
        wfetch(0, wr);
        CP_WAIT0();
        __syncthreads();     // as_s ready; previous-iteration readers done

        for (int dc = 0; dc < 4; dc++) {
#pragma unroll
            for (int i = 0; i < 4; i++)
                *(float4*)(&wu_s[dloc * 68 + (lg + 4 * i) * 4]) = wr[i];
            __syncthreads();

            if (dc < 3) wfetch(dc + 1, wr);   // overlaps compute below

            ull acc[4][4];
#pragma unroll
            for (int j = 0; j < 4; j++)
#pragma unroll
                for (int i = 0; i < 4; i++) acc[j][i] = 0ull;

#pragma unroll
            for (int l4 = 0; l4 < 16; l4++) {
                ulonglong2 xv[4], wv[4];
#pragma unroll
                for (int j = 0; j < 4; j++)
                    xv[j] = *(const ulonglong2*)(&as_s[(tq + 16 * j) * 68 + l4 * 4]);
#pragma unroll
                for (int i = 0; i < 4; i++)
                    wv[i] = *(const ulonglong2*)(&wu_s[(dq * 4 + i) * 68 + l4 * 4]);
#pragma unroll
                for (int j = 0; j < 4; j++)
#pragma unroll
                    for (int i = 0; i < 4; i++) {
                        FFMA2(acc[j][i], xv[j].x, wv[i].x);
                        FFMA2(acc[j][i], xv[j].y, wv[i].y);
                    }
            }

#pragma unroll
            for (int j = 0; j < 4; j++) {
                int s = t0 + tq + 16 * j;
                if (s < cnt) {
                    float w = g_bwgt[e * N_TOK + s];
                    float4 v = make_float4(w * hsum2(acc[j][0]), w * hsum2(acc[j][1]),
                                           w * hsum2(acc[j][2]), w * hsum2(acc[j][3]));
                    y4[(off + s) * (D_MODEL / 4) + dg * 64 + dc * 16 + dq] = v;
                }
            }
            __syncthreads();   // wu_s readers done before next store
        }
    }
}

// ---------------- K5: gather-combine the two pairs per token ------------------
__global__ void k5_combine(float* __restrict__ out) {
    const int n = blockIdx.x;
    const int tid = threadIdx.x;
    const int lane = tid & 31;
    int cc = g_cnt[lane];
    int sc = cc;
#pragma unroll
    for (int o = 1; o < 32; o <<= 1) {
        int v = __shfl_up_sync(0xffffffffu, sc, o);
        if (lane >= o) sc += v;
    }
    int offl = sc - cc;
    int v0 = g_pslot[n * 2 + 0];
    int v1 = g_pslot[n * 2 + 1];
    int p0 = __shfl_sync(0xffffffffu, offl, v0 >> 10) + (v0 & (N_TOK - 1));
    int p1 = __shfl_sync(0xffffffffu, offl, v1 >> 10) + (v1 & (N_TOK - 1));
    const float4* y4 = (const float4*)g_y;
    float4 a = y4[p0 * (D_MODEL / 4) + tid];
    float4 b = y4[p1 * (D_MODEL / 4) + tid];
    ((float4*)out)[n * (D_MODEL / 4) + tid] =
        make_float4(a.x + b.x, a.y + b.y, a.z + b.z, a.w + b.w);
}

// ---------------- launch ------------------------------------------------------
extern "C" void kernel_launch(void* const* d_in, const int* in_sizes, int n_in,
                              void* d_out, int out_size) {
    const float* x        = (const float*)d_in[0];
    const float* w_down   = (const float*)d_in[1];
    const float* router_w = (const float*)d_in[2];
    const float* w_up     = (const float*)d_in[3];
    float* out = (float*)d_out;

    k1_fold<<<128, 256>>>(w_down, router_w);
    k2a_logits<<<dim3(32, LSPLIT), 256>>>(x);
    k2c_route<<<128, 256>>>();
    k3_down<<<dim3(KSPLIT, N_EXP, 2), 256>>>(x, w_down);
    k3g_gelu<<<128, 256>>>(out, out_size > OUT_ELEMS ? 1 : 0);
    k4_up<<<dim3(4, N_EXP, 2), 256>>>(w_up);
    k5_combine<<<N_TOK, 256>>>(out);
}

// round 14
// speedup vs baseline: 1.5785x; 1.5785x over previous
#include <cuda_runtime.h>
#include <math.h>

#define D_MODEL 1024
#define N_EXP   32
#define D_LOW   64
#define N_TOK   1024
#define N_PAIR  (N_TOK * 2)
#define OUT_ELEMS (N_TOK * D_MODEL)
#define KSPLIT  16
#define LSPLIT  8                    // k2a logit k-split
#define PS      (N_PAIR * D_LOW)     // 131072 partials per k-slice

// ---------------- scratch ------------------------------------------------------
__device__ float g_wr[N_EXP * D_MODEL];
__device__ int   g_cnt[N_EXP];
__device__ float g_sumprob[N_EXP];
__device__ int   g_btok[N_EXP * N_TOK];
__device__ float g_bwgt[N_EXP * N_TOK];
__device__ int   g_pslot[N_TOK * 2];
__device__ float g_lgp[LSPLIT * N_TOK * N_EXP];  // k-split logit partials
__device__ float g_actp[KSPLIT * PS];            // k-split down partials (8MB)
__device__ float g_acts[PS];                     // gelu(feats), pair-compact
__device__ float g_y[N_PAIR * D_MODEL];          // weighted per-pair up output

// ---------------- helpers ------------------------------------------------------
__device__ __forceinline__ unsigned f2tf(float f) {
    unsigned r;
    asm("cvt.rna.tf32.f32 %0, %1;" : "=r"(r) : "f"(f));
    return r;
}
// D += A(16x8,row) * B(8x8,col): tf32 inputs, f32 accumulate
#define MMA_TF32(d, a, b0, b1)                                                  \
    asm("mma.sync.aligned.m16n8k8.row.col.f32.tf32.tf32.f32 "                   \
        "{%0,%1,%2,%3},{%4,%5,%6,%7},{%8,%9},{%0,%1,%2,%3};"                    \
        : "+f"((d)[0]), "+f"((d)[1]), "+f"((d)[2]), "+f"((d)[3])                \
        : "r"((a)[0]), "r"((a)[1]), "r"((a)[2]), "r"((a)[3]), "r"(b0), "r"(b1))

__device__ __forceinline__ float dot4(float4 a, float4 b) {
    return a.x * b.x + a.y * b.y + a.z * b.z + a.w * b.w;
}
__device__ __forceinline__ float gelu_exact(float v) {
    return 0.5f * v * (1.0f + erff(v * 0.70710678118654752440f));
}
// exclusive prefix of g_cnt at expert e (all 32 lanes participate)
__device__ __forceinline__ int expert_off(int lane, int e) {
    int cc = g_cnt[lane];
    int sc = cc;
#pragma unroll
    for (int o = 1; o < 32; o <<= 1) {
        int v = __shfl_up_sync(0xffffffffu, sc, o);
        if (lane >= o) sc += v;
    }
    return __shfl_sync(0xffffffffu, sc - cc, e);
}

// ---------------- K1: fold router_w into w_down -> g_wr; zero accumulators ----
__global__ void k1_fold(const float* __restrict__ w_down,
                        const float* __restrict__ router_w) {
    __shared__ float rs[D_LOW];
    int tid = threadIdx.x;
    if (blockIdx.x == 0 && tid < N_EXP) { g_cnt[tid] = 0; g_sumprob[tid] = 0.f; }
    if (tid < D_LOW) rs[tid] = router_w[tid];
    __syncthreads();
    int idx = blockIdx.x * 256 + tid;
    int e = idx >> 10;
    int d = idx & (D_MODEL - 1);
    const float* wb = w_down + (e << 6) * D_MODEL + d;
    float acc = 0.f;
#pragma unroll 8
    for (int l = 0; l < D_LOW; l++)
        acc = fmaf(wb[l * D_MODEL], rs[l], acc);
    g_wr[idx] = acc;
}

// ---------------- K2a: logits GEMM (exact fp32), k-split by 8 ------------------
__global__ __launch_bounds__(256) void k2a_logits(const float* __restrict__ x) {
    __shared__ float4 xs4[32 * 33];
    __shared__ float4 wr4[32 * 33];
    const int tid = threadIdx.x;
    const int tt = blockIdx.x, kc = blockIdx.y;
    const int t = tid & 31, eg = tid >> 5;
    const float4* x4 = (const float4*)x;
    const float4* w4 = (const float4*)g_wr;

    const int k0q = kc * 32;
#pragma unroll
    for (int i = 0; i < 4; i++) {
        int j = tid + i * 256;
        int r = j >> 5, c = j & 31;
        xs4[r * 33 + c] = x4[(tt * 32 + r) * (D_MODEL / 4) + k0q + c];
        wr4[r * 33 + c] = w4[r * (D_MODEL / 4) + k0q + c];
    }
    __syncthreads();
    float acc0 = 0.f, acc1 = 0.f, acc2 = 0.f, acc3 = 0.f;
#pragma unroll 8
    for (int k4 = 0; k4 < 32; k4++) {
        float4 xv = xs4[t * 33 + k4];
        acc0 += dot4(xv, wr4[(eg * 4 + 0) * 33 + k4]);
        acc1 += dot4(xv, wr4[(eg * 4 + 1) * 33 + k4]);
        acc2 += dot4(xv, wr4[(eg * 4 + 2) * 33 + k4]);
        acc3 += dot4(xv, wr4[(eg * 4 + 3) * 33 + k4]);
    }
    const int n = tt * 32 + t;
    ((float4*)g_lgp)[kc * (N_TOK * N_EXP / 4) + n * 8 + eg] =
        make_float4(acc0, acc1, acc2, acc3);
}

// ---------------- K2c: reduce partials + softmax + top-2 + bucketize ----------
__global__ void k2c_route() {
    const int tid = threadIdx.x;
    const int lane = tid & 31, warp = tid >> 5;
    const int n = blockIdx.x * 8 + warp;

    float v = 0.f;
#pragma unroll
    for (int p = 0; p < LSPLIT; p++)
        v += g_lgp[p * (N_TOK * N_EXP) + n * N_EXP + lane];

    float m = v;
#pragma unroll
    for (int o = 16; o; o >>= 1) m = fmaxf(m, __shfl_xor_sync(0xffffffffu, m, o));
    float ex = expf(v - m);
    float s = ex;
#pragma unroll
    for (int o = 16; o; o >>= 1) s += __shfl_xor_sync(0xffffffffu, s, o);
    float prob = ex / s;
    atomicAdd(&g_sumprob[lane], prob);

    float bv = v; int bi = lane;
#pragma unroll
    for (int o = 16; o; o >>= 1) {
        float ov = __shfl_xor_sync(0xffffffffu, bv, o);
        int   oi = __shfl_xor_sync(0xffffffffu, bi, o);
        if (ov > bv || (ov == bv && oi < bi)) { bv = ov; bi = oi; }
    }
    int i0 = bi;
    float v2 = (lane == i0) ? -INFINITY : v;
    float bv2 = v2; int bi2 = lane;
#pragma unroll
    for (int o = 16; o; o >>= 1) {
        float ov = __shfl_xor_sync(0xffffffffu, bv2, o);
        int   oi = __shfl_xor_sync(0xffffffffu, bi2, o);
        if (ov > bv2 || (ov == bv2 && oi < bi2)) { bv2 = ov; bi2 = oi; }
    }
    int i1 = bi2;
    float p0 = __shfl_sync(0xffffffffu, prob, i0);
    float p1 = __shfl_sync(0xffffffffu, prob, i1);
    if (lane == 0) {
        float inv = 1.f / (p0 + p1);
        int s0 = atomicAdd(&g_cnt[i0], 1);
        g_btok[i0 * N_TOK + s0] = n;
        g_bwgt[i0 * N_TOK + s0] = p0 * inv;
        g_pslot[n * 2 + 0] = i0 * N_TOK + s0;
        int s1 = atomicAdd(&g_cnt[i1], 1);
        g_btok[i1 * N_TOK + s1] = n;
        g_bwgt[i1 * N_TOK + s1] = p1 * inv;
        g_pslot[n * 2 + 1] = i1 * N_TOK + s1;
    }
}

// ---------------- K3: down-proj partials via tf32 mma.sync ---------------------
// grid (16 k-slices, 32 experts, 2 token-tiles), 256 threads.
// Block: 64 tok x 64 l x 64 k. Warp w: tokens [(w&3)*16,+16), l [(w>>2)*32,+32).
__global__ __launch_bounds__(256, 3)
void k3_down(const float* __restrict__ x, const float* __restrict__ w_down) {
    __shared__ float ws[D_LOW * 68];      // [64 l][64 k + pad]
    __shared__ float xs[64 * 68];         // [64 tok][64 k + pad]

    const int e = blockIdx.y;
    const int ks = blockIdx.x;
    const int cnt = g_cnt[e];
    const int tile0 = blockIdx.z * 64;
    if (tile0 >= cnt) return;
    const int tid = threadIdx.x;
    const int off = expert_off(tid & 31, e);

    const float4* wd4 = (const float4*)w_down;
#pragma unroll
    for (int i = 0; i < 4; i++) {
        int j = tid + i * 256;
        int l = j >> 4, cq = j & 15;
        *(float4*)(ws + l * 68 + cq * 4) =
            wd4[(e * D_LOW + l) * (D_MODEL / 4) + ks * 16 + cq];
    }

    const int lane = tid & 31, warp = tid >> 5;
    const int mb = (warp & 3) * 16;       // token block
    const int nb = (warp >> 2) * 32;      // l block
    const int grp = lane >> 2, tig = lane & 3;
    const int r0 = tid >> 4, cq0 = tid & 15;
    const float4* x4g = (const float4*)x;

    for (int t0 = tile0; t0 < cnt; t0 += 128) {
#pragma unroll
        for (int j = 0; j < 4; j++) {
            int idx = t0 + r0 + 16 * j; if (idx >= cnt) idx = cnt - 1;
            *(float4*)(xs + (r0 + 16 * j) * 68 + cq0 * 4) =
                x4g[g_btok[e * N_TOK + idx] * (D_MODEL / 4) + ks * 16 + cq0];
        }
        __syncthreads();

        float acc[4][4];
#pragma unroll
        for (int nt = 0; nt < 4; nt++)
#pragma unroll
            for (int c = 0; c < 4; c++) acc[nt][c] = 0.f;

#pragma unroll
        for (int k0 = 0; k0 < 64; k0 += 8) {
            unsigned a[4];
            a[0] = f2tf(xs[(mb + grp    ) * 68 + k0 + tig    ]);
            a[1] = f2tf(xs[(mb + grp + 8) * 68 + k0 + tig    ]);
            a[2] = f2tf(xs[(mb + grp    ) * 68 + k0 + tig + 4]);
            a[3] = f2tf(xs[(mb + grp + 8) * 68 + k0 + tig + 4]);
#pragma unroll
            for (int nt = 0; nt < 4; nt++) {
                unsigned b0 = f2tf(ws[(nb + nt * 8 + grp) * 68 + k0 + tig    ]);
                unsigned b1 = f2tf(ws[(nb + nt * 8 + grp) * 68 + k0 + tig + 4]);
                MMA_TF32(acc[nt], a, b0, b1);
            }
        }

        // store D fragments: row = mb+grp(+8), col = nb + nt*8 + 2*tig(+1)
#pragma unroll
        for (int nt = 0; nt < 4; nt++) {
#pragma unroll
            for (int h = 0; h < 2; h++) {
                int s = t0 + mb + grp + 8 * h;
                if (s < cnt) {
                    int col = nb + nt * 8 + 2 * tig;
                    *(float2*)&g_actp[((ks * N_PAIR + off + s) << 6) + col] =
                        make_float2(acc[nt][2 * h], acc[nt][2 * h + 1]);
                }
            }
        }
        __syncthreads();
    }
}

// ---------------- K3g: sum 16 k-slices + GELU (+ aux loss in block 0) ---------
__global__ void k3g_gelu(float* out, int write_aux) {
    int tid = threadIdx.x;
    if (blockIdx.x == 0 && tid < 32 && write_aux) {
        float v = g_sumprob[tid] * (float)g_cnt[tid];
#pragma unroll
        for (int o = 16; o; o >>= 1) v += __shfl_xor_sync(0xffffffffu, v, o);
        if (tid == 0)
            out[OUT_ELEMS] = (float)N_EXP * v / ((float)N_TOK * (float)N_TOK);
    }
    int i = blockIdx.x * 256 + tid;               // 128*256 = PS/4
    const float4* ap4 = (const float4*)g_actp;
    float4 s = ap4[i];
#pragma unroll
    for (int k = 1; k < KSPLIT; k++) {
        float4 v = ap4[k * (PS / 4) + i];
        s.x += v.x; s.y += v.y; s.z += v.z; s.w += v.w;
    }
    ((float4*)g_acts)[i] = make_float4(gelu_exact(s.x), gelu_exact(s.y),
                                       gelu_exact(s.z), gelu_exact(s.w));
}

// ---------------- K4: up-proj via tf32 mma.sync --------------------------------
// grid (16 d-tiles, 32 experts, 2 token-tiles), 256 threads.
// Block: 64 tok x 64 d x 64 l. Warp w: tokens [(w&3)*16), d [(w>>2)*32).
__global__ __launch_bounds__(256, 3)
void k4_up(const float* __restrict__ w_up) {
    __shared__ float wu_s[64 * 68];       // [64 d][64 l + pad]  (transposed)
    __shared__ float as_s[64 * 68];       // [64 tok][64 l + pad]

    const int e = blockIdx.y;
    const int dt = blockIdx.x;
    const int cnt = g_cnt[e];
    const int tile0 = blockIdx.z * 64;
    if (tile0 >= cnt) return;
    const int tid = threadIdx.x;
    const int off = expert_off(tid & 31, e);

    // transpose w_up[e][l][dt*64 + d] -> wu_s[d][l]
#pragma unroll
    for (int i = 0; i < 4; i++) {
        int j = tid + i * 256;
        int d = j & 63, lg = j >> 6;
        const float* base = w_up + (e * D_LOW + lg * 4) * D_MODEL + dt * 64 + d;
        *(float4*)(wu_s + d * 68 + lg * 4) =
            make_float4(base[0], base[D_MODEL], base[2 * D_MODEL], base[3 * D_MODEL]);
    }

    const int lane = tid & 31, warp = tid >> 5;
    const int mb = (warp & 3) * 16;       // token block
    const int nb = (warp >> 2) * 32;      // d block
    const int grp = lane >> 2, tig = lane & 3;
    const int r0 = tid >> 4, cq0 = tid & 15;
    const float4* a4g = (const float4*)g_acts;

    for (int t0 = tile0; t0 < cnt; t0 += 128) {
#pragma unroll
        for (int j = 0; j < 4; j++) {
            int idx = t0 + r0 + 16 * j; if (idx >= cnt) idx = cnt - 1;
            *(float4*)(as_s + (r0 + 16 * j) * 68 + cq0 * 4) =
                a4g[(off + idx) * (D_LOW / 4) + cq0];
        }
        __syncthreads();

        float acc[4][4];
#pragma unroll
        for (int nt = 0; nt < 4; nt++)
#pragma unroll
            for (int c = 0; c < 4; c++) acc[nt][c] = 0.f;

#pragma unroll
        for (int k0 = 0; k0 < 64; k0 += 8) {
            unsigned a[4];
            a[0] = f2tf(as_s[(mb + grp    ) * 68 + k0 + tig    ]);
            a[1] = f2tf(as_s[(mb + grp + 8) * 68 + k0 + tig    ]);
            a[2] = f2tf(as_s[(mb + grp    ) * 68 + k0 + tig + 4]);
            a[3] = f2tf(as_s[(mb + grp + 8) * 68 + k0 + tig + 4]);
#pragma unroll
            for (int nt = 0; nt < 4; nt++) {
                unsigned b0 = f2tf(wu_s[(nb + nt * 8 + grp) * 68 + k0 + tig    ]);
                unsigned b1 = f2tf(wu_s[(nb + nt * 8 + grp) * 68 + k0 + tig + 4]);
                MMA_TF32(acc[nt], a, b0, b1);
            }
        }

        // store: row token s = t0+mb+grp(+8), col d = dt*64 + nb + nt*8 + 2*tig
#pragma unroll
        for (int h = 0; h < 2; h++) {
            int s = t0 + mb + grp + 8 * h;
            if (s < cnt) {
                float w = g_bwgt[e * N_TOK + s];
                float* yrow = g_y + (off + s) * D_MODEL + dt * 64;
#pragma unroll
                for (int nt = 0; nt < 4; nt++) {
                    int col = nb + nt * 8 + 2 * tig;
                    *(float2*)&yrow[col] =
                        make_float2(w * acc[nt][2 * h], w * acc[nt][2 * h + 1]);
                }
            }
        }
        __syncthreads();
    }
}

// ---------------- K5: gather-combine the two pairs per token ------------------
__global__ void k5_combine(float* __restrict__ out) {
    const int n = blockIdx.x;
    const int tid = threadIdx.x;
    const int lane = tid & 31;
    int cc = g_cnt[lane];
    int sc = cc;
#pragma unroll
    for (int o = 1; o < 32; o <<= 1) {
        int v = __shfl_up_sync(0xffffffffu, sc, o);
        if (lane >= o) sc += v;
    }
    int offl = sc - cc;
    int v0 = g_pslot[n * 2 + 0];
    int v1 = g_pslot[n * 2 + 1];
    int p0 = __shfl_sync(0xffffffffu, offl, v0 >> 10) + (v0 & (N_TOK - 1));
    int p1 = __shfl_sync(0xffffffffu, offl, v1 >> 10) + (v1 & (N_TOK - 1));
    const float4* y4 = (const float4*)g_y;
    float4 a = y4[p0 * (D_MODEL / 4) + tid];
    float4 b = y4[p1 * (D_MODEL / 4) + tid];
    ((float4*)out)[n * (D_MODEL / 4) + tid] =
        make_float4(a.x + b.x, a.y + b.y, a.z + b.z, a.w + b.w);
}

// ---------------- launch ------------------------------------------------------
extern "C" void kernel_launch(void* const* d_in, const int* in_sizes, int n_in,
                              void* d_out, int out_size) {
    const float* x        = (const float*)d_in[0];
    const float* w_down   = (const float*)d_in[1];
    const float* router_w = (const float*)d_in[2];
    const float* w_up     = (const float*)d_in[3];
    float* out = (float*)d_out;

    k1_fold<<<128, 256>>>(w_down, router_w);
    k2a_logits<<<dim3(32, LSPLIT), 256>>>(x);
    k2c_route<<<128, 256>>>();
    k3_down<<<dim3(KSPLIT, N_EXP, 2), 256>>>(x, w_down);
    k3g_gelu<<<128, 256>>>(out, out_size > OUT_ELEMS ? 1 : 0);
    k4_up<<<dim3(16, N_EXP, 2), 256>>>(w_up);
    k5_combine<<<N_TOK, 256>>>(out);
}